// round 3
// baseline (speedup 1.0000x reference)
#include <cuda_runtime.h>
#include <cuda_fp16.h>
#include <cstdint>

// ---------------------------------------------------------------------------
// Problem constants
// ---------------------------------------------------------------------------
#define B_ROWS 4096
#define D_DIM  512
#define C_DIM  20000

#define BM 128
#define BN 128
#define BK 64                   // 64 fp16 = 128B rows (SW128 atom)
#define NK (D_DIM / BK)         // 8 k-iterations
#define STAGES 3
#define THREADS 256

#define STAGE_BYTES ((BM + BN) * BK * 2)   // 32768
#define SMEM_BYTES  (STAGES * STAGE_BYTES + 1024)

static __device__ __half g_f16[(size_t)B_ROWS * D_DIM];   // normalized feat, fp16
static __device__ __half g_w16[(size_t)C_DIM * D_DIM];    // normalized weights, fp16

// ArcFace constants
#define AF_SCALE  30.0f
#define AF_COSM   0.87758256189037271612f   // cos(0.5)
#define AF_SINM   0.47942553860420300027f   // sin(0.5)
#define AF_THRESH (-0.87758256189037271612f)
#define AF_EXTV   (-0.23971276930210150013f) // -0.5*sin(0.5)

// ---------------------------------------------------------------------------
// PTX helpers (all non-'a' features: sm_80/sm_75 baseline)
// ---------------------------------------------------------------------------
__device__ __forceinline__ uint32_t smem_u32(const void* p) {
    uint32_t a;
    asm("{ .reg .u64 t; cvta.to.shared.u64 t, %1; cvt.u32.u64 %0, t; }"
        : "=r"(a) : "l"(p));
    return a;
}

__device__ __forceinline__ uint32_t sw128(uint32_t off) {
    return off ^ ((off >> 3) & 0x70);
}

__device__ __forceinline__ void cp_async16(uint32_t dst, const void* src,
                                           uint32_t ssize) {
    asm volatile("cp.async.cg.shared.global [%0], [%1], 16, %2;"
                 :: "r"(dst), "l"(src), "r"(ssize));
}
#define CP_COMMIT() asm volatile("cp.async.commit_group;" ::: "memory")
#define CP_WAIT(n)  asm volatile("cp.async.wait_group %0;" :: "n"(n) : "memory")

#define LDSM_X4(r, addr) \
    asm volatile("ldmatrix.sync.aligned.m8n8.x4.shared.b16 {%0,%1,%2,%3}, [%4];" \
        : "=r"((r)[0]), "=r"((r)[1]), "=r"((r)[2]), "=r"((r)[3]) : "r"(addr))
#define LDSM_X2(r, addr) \
    asm volatile("ldmatrix.sync.aligned.m8n8.x2.shared.b16 {%0,%1}, [%2];" \
        : "=r"((r)[0]), "=r"((r)[1]) : "r"(addr))

__device__ __forceinline__ void mma_16816(float* d, const uint32_t* a,
                                          const uint32_t* b) {
    asm volatile(
        "mma.sync.aligned.m16n8k16.row.col.f32.f16.f16.f32 "
        "{%0,%1,%2,%3}, {%4,%5,%6,%7}, {%8,%9}, {%0,%1,%2,%3};"
        : "+f"(d[0]), "+f"(d[1]), "+f"(d[2]), "+f"(d[3])
        : "r"(a[0]), "r"(a[1]), "r"(a[2]), "r"(a[3]), "r"(b[0]), "r"(b[1]));
}

// ---------------------------------------------------------------------------
// Kernel 1/2: row L2-normalize fp32 -> fp16 (one block of 128 threads per row)
// ---------------------------------------------------------------------------
__global__ void norm_rows_kernel(const float* __restrict__ src,
                                 __half* __restrict__ dst) {
    const int row = blockIdx.x;
    const int tid = threadIdx.x;
    const float4 v = reinterpret_cast<const float4*>(src + (size_t)row * D_DIM)[tid];
    float ss = v.x * v.x + v.y * v.y + v.z * v.z + v.w * v.w;
    #pragma unroll
    for (int o = 16; o; o >>= 1) ss += __shfl_xor_sync(0xFFFFFFFFu, ss, o);
    __shared__ float ws[4];
    if ((tid & 31) == 0) ws[tid >> 5] = ss;
    __syncthreads();
    const float inv = rsqrtf(ws[0] + ws[1] + ws[2] + ws[3]);
    __half2 h0 = __floats2half2_rn(v.x * inv, v.y * inv);
    __half2 h1 = __floats2half2_rn(v.z * inv, v.w * inv);
    uint2 pk;
    pk.x = *reinterpret_cast<uint32_t*>(&h0);
    pk.y = *reinterpret_cast<uint32_t*>(&h1);
    reinterpret_cast<uint2*>(dst + (size_t)row * D_DIM)[tid] = pk;
}

// ---------------------------------------------------------------------------
// Tile loader: A[128x64] + B[128x64] fp16 into SW128-swizzled smem via cp.async
// ---------------------------------------------------------------------------
__device__ __forceinline__ void load_tiles(uint32_t sA, uint32_t sB,
                                           int m0, int n0, int kk, int tid) {
    #pragma unroll
    for (int i = 0; i < 4; i++) {
        int s = tid + i * THREADS;            // 0..1023
        int row = s >> 3, c16 = s & 7;
        const __half* src = g_f16 + (size_t)(m0 + row) * D_DIM + kk + c16 * 8;
        cp_async16(sA + sw128((uint32_t)(row * 128 + c16 * 16)), src, 16u);
    }
    #pragma unroll
    for (int i = 0; i < 4; i++) {
        int s = tid + i * THREADS;
        int row = s >> 3, c16 = s & 7;
        int n = n0 + row;
        int nc = (n < C_DIM) ? n : 0;
        const __half* src = g_w16 + (size_t)nc * D_DIM + kk + c16 * 8;
        cp_async16(sB + sw128((uint32_t)(row * 128 + c16 * 16)), src,
                   (n < C_DIM) ? 16u : 0u);
    }
}

// ---------------------------------------------------------------------------
// Kernel 3: mma.sync GEMM, 128x128 block tile, 3-stage cp.async pipeline.
// Epilogue stores cos and 30*cos directly from fragments (float2).
// ---------------------------------------------------------------------------
__global__ void __launch_bounds__(THREADS)
arcface_gemm_kernel(float* __restrict__ cos_out, float* __restrict__ marg_out) {
    extern __shared__ char dsmem[];
    uint32_t sbase = (smem_u32(dsmem) + 1023u) & ~1023u;

    const int tid  = threadIdx.x;
    const int lane = tid & 31;
    const int wid  = tid >> 5;
    const int warp_m = wid & 1;     // 0..1  (64-row slab)
    const int warp_n = wid >> 1;    // 0..3  (32-col slab)
    const int n0 = blockIdx.x * BN;
    const int m0 = blockIdx.y * BM;

    float acc[4][4][4];
    #pragma unroll
    for (int mt = 0; mt < 4; mt++)
        #pragma unroll
        for (int nt = 0; nt < 4; nt++)
            #pragma unroll
            for (int e = 0; e < 4; e++) acc[mt][nt][e] = 0.0f;

    // prologue: fill stages 0,1
    load_tiles(sbase + 0 * STAGE_BYTES, sbase + 0 * STAGE_BYTES + BM * BK * 2,
               m0, n0, 0, tid);
    CP_COMMIT();
    load_tiles(sbase + 1 * STAGE_BYTES, sbase + 1 * STAGE_BYTES + BM * BK * 2,
               m0, n0, BK, tid);
    CP_COMMIT();

    // lane-constant pieces of the swizzled ldmatrix addresses
    const uint32_t a_lane_off =
        (uint32_t)((warp_m * 64 + (lane & 15)) * 128 + (lane >> 4) * 16);
    const uint32_t b_lane_off =
        (uint32_t)((warp_n * 32 + (lane & 7)) * 128 + ((lane >> 3) & 1) * 16);

    for (int k = 0; k < NK; k++) {
        CP_WAIT(1);
        __syncthreads();

        if (k + STAGES - 1 < NK) {
            int st = (k + STAGES - 1) % STAGES;
            load_tiles(sbase + st * STAGE_BYTES,
                       sbase + st * STAGE_BYTES + BM * BK * 2,
                       m0, n0, (k + STAGES - 1) * BK, tid);
        }
        CP_COMMIT();

        const uint32_t sA = sbase + (k % STAGES) * STAGE_BYTES;
        const uint32_t sB = sA + BM * BK * 2;

        #pragma unroll
        for (int ks = 0; ks < 4; ks++) {
            uint32_t a_frag[4][4];
            #pragma unroll
            for (int mt = 0; mt < 4; mt++)
                LDSM_X4(a_frag[mt],
                        sA + sw128(a_lane_off + (uint32_t)(mt * 16 * 128 + ks * 32)));
            uint32_t b_frag[4][2];
            #pragma unroll
            for (int nt = 0; nt < 4; nt++)
                LDSM_X2(b_frag[nt],
                        sB + sw128(b_lane_off + (uint32_t)(nt * 8 * 128 + ks * 32)));
            #pragma unroll
            for (int mt = 0; mt < 4; mt++)
                #pragma unroll
                for (int nt = 0; nt < 4; nt++)
                    mma_16816(acc[mt][nt], a_frag[mt], b_frag[nt]);
        }
    }

    // --- epilogue: direct float2 stores of cos and 30*cos ---
    const int mrow  = m0 + warp_m * 64 + (lane >> 2);
    const int ncol0 = n0 + warp_n * 32 + (lane & 3) * 2;
    #pragma unroll
    for (int mt = 0; mt < 4; mt++) {
        #pragma unroll
        for (int nt = 0; nt < 4; nt++) {
            int n = ncol0 + nt * 8;
            if (n >= C_DIM) continue;
            int m = mrow + mt * 16;
            size_t o1 = (size_t)m * C_DIM + n;
            size_t o2 = (size_t)(m + 8) * C_DIM + n;
            float2 c1 = make_float2(acc[mt][nt][0], acc[mt][nt][1]);
            float2 c2 = make_float2(acc[mt][nt][2], acc[mt][nt][3]);
            float2 s1 = make_float2(AF_SCALE * c1.x, AF_SCALE * c1.y);
            float2 s2 = make_float2(AF_SCALE * c2.x, AF_SCALE * c2.y);
            *reinterpret_cast<float2*>(cos_out + o1)  = c1;
            *reinterpret_cast<float2*>(cos_out + o2)  = c2;
            *reinterpret_cast<float2*>(marg_out + o1) = s1;
            *reinterpret_cast<float2*>(marg_out + o2) = s2;
        }
    }
}

// ---------------------------------------------------------------------------
// Kernel 4: fix marginal_logits at the label column (4096 elements)
// NOTE: label is int32 on device (JAX x64 disabled downcasts int64 -> int32).
// ---------------------------------------------------------------------------
__global__ void arcface_fixup_kernel(const int* __restrict__ label,
                                     const float* __restrict__ cos_out,
                                     float* __restrict__ marg_out) {
    int i = blockIdx.x * blockDim.x + threadIdx.x;
    if (i >= B_ROWS) return;
    int j = label[i];
    if (j < 0 || j >= C_DIM) return;   // defensive clamp
    float c = cos_out[(size_t)i * C_DIM + (size_t)j];
    float m;
    if (c > AF_THRESH) {
        float s = sqrtf(fmaxf(0.0f, 1.0f - c * c));
        m = AF_SCALE * (c * AF_COSM - s * AF_SINM);
    } else {
        m = AF_SCALE * (c + AF_EXTV);
    }
    marg_out[(size_t)i * C_DIM + (size_t)j] = m;
}

// ---------------------------------------------------------------------------
// Launch
// ---------------------------------------------------------------------------
extern "C" void kernel_launch(void* const* d_in, const int* in_sizes, int n_in,
                              void* d_out, int out_size) {
    const float* feat  = (const float*)d_in[0];
    const int*   label = (const int*)d_in[1];
    const float* wts   = (const float*)d_in[2];
    float* cos_out  = (float*)d_out;
    float* marg_out = cos_out + (size_t)B_ROWS * C_DIM;

    __half* f16p = nullptr;
    __half* w16p = nullptr;
    cudaGetSymbolAddress((void**)&f16p, g_f16);
    cudaGetSymbolAddress((void**)&w16p, g_w16);

    norm_rows_kernel<<<B_ROWS, 128>>>(feat, f16p);
    norm_rows_kernel<<<C_DIM, 128>>>(wts, w16p);

    cudaFuncSetAttribute(arcface_gemm_kernel,
                         cudaFuncAttributeMaxDynamicSharedMemorySize,
                         SMEM_BYTES);

    dim3 grid((C_DIM + BN - 1) / BN, B_ROWS / BM);   // (157, 32)
    arcface_gemm_kernel<<<grid, THREADS, SMEM_BYTES>>>(cos_out, marg_out);

    arcface_fixup_kernel<<<(B_ROWS + 255) / 256, 256>>>(label, cos_out, marg_out);
}